// round 3
// baseline (speedup 1.0000x reference)
#include <cuda_runtime.h>

// Cross attention: B=8, Tq=Tk=2048, D=1024, fp32.
// out = softmax((tgt@Wq^T+bq)(src@Wk^T+bk)^T / 32) @ (src@Wv^T+bv) @ Wo^T + bo

#define BATCH 8
#define TSEQ  2048
#define EMB   1024
#define MTOT  (BATCH * TSEQ)   // 16384

// Scratch (allocation-free rule: __device__ globals)
__device__ float g_Q[(size_t)MTOT * EMB];
__device__ float g_K[(size_t)MTOT * EMB];
__device__ float g_V[(size_t)MTOT * EMB];
__device__ float g_O[(size_t)MTOT * EMB];
__device__ float g_S[(size_t)BATCH * TSEQ * TSEQ];

// ---------------------------------------------------------------------------
// Classic 128x128x8 SGEMM, 256 threads, 8x8 micro-tile per thread.
// NT == true : B is [N, K] row-major (x @ W^T and Q @ K^T)
// NT == false: B is [K, N] row-major (P @ V)
// All problem dims here are multiples of the tile sizes -> no bounds checks.
// ---------------------------------------------------------------------------
template <bool NT, bool HAS_BIAS>
__global__ __launch_bounds__(256, 2)
void sgemm_kernel(const float* __restrict__ A, const float* __restrict__ B,
                  const float* __restrict__ bias, float* __restrict__ C,
                  int M, int N, int K, float alpha,
                  size_t strideA, size_t strideB, size_t strideC)
{
    const int tid = threadIdx.x;
    A += (size_t)blockIdx.z * strideA;
    B += (size_t)blockIdx.z * strideB;
    C += (size_t)blockIdx.z * strideC;

    const int m0 = blockIdx.y * 128;
    const int n0 = blockIdx.x * 128;

    __shared__ float As[8][128];
    __shared__ float Bs[8][128];

    const int tx = tid & 15;   // 0..15 -> 8 cols each
    const int ty = tid >> 4;   // 0..15 -> 8 rows each

    // A/B(NT) load coords: 128 rows x 2 float4 in k
    const int ld_row  = tid >> 1;        // 0..127
    const int ld_col  = (tid & 1) * 4;   // 0 or 4
    // B(NN) load coords: 8 k-rows x 32 float4 in n
    const int bn_k    = tid >> 5;        // 0..7
    const int bn_n    = (tid & 31) * 4;  // 0..124

    float acc[8][8];
#pragma unroll
    for (int i = 0; i < 8; i++)
#pragma unroll
        for (int j = 0; j < 8; j++) acc[i][j] = 0.0f;

    for (int k0 = 0; k0 < K; k0 += 8) {
        float4 av = *reinterpret_cast<const float4*>(
            A + (size_t)(m0 + ld_row) * K + k0 + ld_col);
        float4 bv;
        if (NT) {
            bv = *reinterpret_cast<const float4*>(
                B + (size_t)(n0 + ld_row) * K + k0 + ld_col);
        } else {
            bv = *reinterpret_cast<const float4*>(
                B + (size_t)(k0 + bn_k) * N + n0 + bn_n);
        }

        __syncthreads();   // previous iteration's reads done
        As[ld_col + 0][ld_row] = av.x;
        As[ld_col + 1][ld_row] = av.y;
        As[ld_col + 2][ld_row] = av.z;
        As[ld_col + 3][ld_row] = av.w;
        if (NT) {
            Bs[ld_col + 0][ld_row] = bv.x;
            Bs[ld_col + 1][ld_row] = bv.y;
            Bs[ld_col + 2][ld_row] = bv.z;
            Bs[ld_col + 3][ld_row] = bv.w;
        } else {
            *reinterpret_cast<float4*>(&Bs[bn_k][bn_n]) = bv;
        }
        __syncthreads();

#pragma unroll
        for (int k = 0; k < 8; k++) {
            float ra[8], rb[8];
#pragma unroll
            for (int i = 0; i < 8; i++) ra[i] = As[k][ty * 8 + i];
#pragma unroll
            for (int j = 0; j < 8; j++) rb[j] = Bs[k][tx * 8 + j];
#pragma unroll
            for (int i = 0; i < 8; i++)
#pragma unroll
                for (int j = 0; j < 8; j++) acc[i][j] += ra[i] * rb[j];
        }
    }

#pragma unroll
    for (int i = 0; i < 8; i++) {
        const size_t row = (size_t)(m0 + ty * 8 + i);
        float4 o0, o1;
        float* a = acc[i];
        o0.x = a[0] * alpha; o0.y = a[1] * alpha;
        o0.z = a[2] * alpha; o0.w = a[3] * alpha;
        o1.x = a[4] * alpha; o1.y = a[5] * alpha;
        o1.z = a[6] * alpha; o1.w = a[7] * alpha;
        const int col = n0 + tx * 8;
        if (HAS_BIAS) {
            o0.x += bias[col + 0]; o0.y += bias[col + 1];
            o0.z += bias[col + 2]; o0.w += bias[col + 3];
            o1.x += bias[col + 4]; o1.y += bias[col + 5];
            o1.z += bias[col + 6]; o1.w += bias[col + 7];
        }
        *reinterpret_cast<float4*>(C + row * N + col)     = o0;
        *reinterpret_cast<float4*>(C + row * N + col + 4) = o1;
    }
}

// ---------------------------------------------------------------------------
// Row softmax over rows of length 2048. One block (256 thr) per row.
// Block reductions broadcast the result to ALL threads via shared memory
// (the R0 bug: shfl-based broadcast only reached warp 0).
// ---------------------------------------------------------------------------
__device__ __forceinline__ float block_reduce_max(float v) {
    __shared__ float sh[8];
    __shared__ float res;
    const int lane = threadIdx.x & 31;
    const int warp = threadIdx.x >> 5;
#pragma unroll
    for (int o = 16; o > 0; o >>= 1)
        v = fmaxf(v, __shfl_xor_sync(0xffffffffu, v, o));
    if (lane == 0) sh[warp] = v;
    __syncthreads();
    if (warp == 0) {
        float w = (lane < 8) ? sh[lane] : -3.0e38f;
#pragma unroll
        for (int o = 4; o > 0; o >>= 1)
            w = fmaxf(w, __shfl_xor_sync(0xffffffffu, w, o));
        if (lane == 0) res = w;
    }
    __syncthreads();
    return res;
}

__device__ __forceinline__ float block_reduce_sum(float v) {
    __shared__ float sh[8];
    __shared__ float res;
    const int lane = threadIdx.x & 31;
    const int warp = threadIdx.x >> 5;
#pragma unroll
    for (int o = 16; o > 0; o >>= 1)
        v += __shfl_xor_sync(0xffffffffu, v, o);
    if (lane == 0) sh[warp] = v;
    __syncthreads();
    if (warp == 0) {
        float w = (lane < 8) ? sh[lane] : 0.0f;
#pragma unroll
        for (int o = 4; o > 0; o >>= 1)
            w += __shfl_xor_sync(0xffffffffu, w, o);
        if (lane == 0) res = w;
    }
    __syncthreads();
    return res;
}

__global__ __launch_bounds__(256)
void softmax_kernel(float* __restrict__ S)
{
    float4* row = reinterpret_cast<float4*>(S + (size_t)blockIdx.x * TSEQ);
    const int t = threadIdx.x;

    float4 v0 = row[t];
    float4 v1 = row[t + 256];

    float mx = fmaxf(fmaxf(fmaxf(v0.x, v0.y), fmaxf(v0.z, v0.w)),
                     fmaxf(fmaxf(v1.x, v1.y), fmaxf(v1.z, v1.w)));
    mx = block_reduce_max(mx);

    v0.x = __expf(v0.x - mx); v0.y = __expf(v0.y - mx);
    v0.z = __expf(v0.z - mx); v0.w = __expf(v0.w - mx);
    v1.x = __expf(v1.x - mx); v1.y = __expf(v1.y - mx);
    v1.z = __expf(v1.z - mx); v1.w = __expf(v1.w - mx);

    float s = (v0.x + v0.y + v0.z + v0.w) + (v1.x + v1.y + v1.z + v1.w);
    s = block_reduce_sum(s);
    const float inv = 1.0f / s;

    v0.x *= inv; v0.y *= inv; v0.z *= inv; v0.w *= inv;
    v1.x *= inv; v1.y *= inv; v1.z *= inv; v1.w *= inv;
    row[t]       = v0;
    row[t + 256] = v1;
}

// ---------------------------------------------------------------------------
extern "C" void kernel_launch(void* const* d_in, const int* in_sizes, int n_in,
                              void* d_out, int out_size)
{
    const float* target = (const float*)d_in[0];
    const float* source = (const float*)d_in[1];
    const float* Wq = (const float*)d_in[2];
    const float* bq = (const float*)d_in[3];
    const float* Wk = (const float*)d_in[4];
    const float* bk = (const float*)d_in[5];
    const float* Wv = (const float*)d_in[6];
    const float* bv = (const float*)d_in[7];
    const float* Wo = (const float*)d_in[8];
    const float* bo = (const float*)d_in[9];
    float* out = (float*)d_out;

    float *Q, *K, *V, *O, *S;
    cudaGetSymbolAddress((void**)&Q, g_Q);
    cudaGetSymbolAddress((void**)&K, g_K);
    cudaGetSymbolAddress((void**)&V, g_V);
    cudaGetSymbolAddress((void**)&O, g_O);
    cudaGetSymbolAddress((void**)&S, g_S);

    const dim3 blk(256);
    const float scale = 1.0f / 32.0f;  // 1/sqrt(1024)

    // Projections: [16384,1024] = X[16384,1024] @ W^T[1024,1024] + b
    {
        dim3 grid(EMB / 128, MTOT / 128, 1);
        sgemm_kernel<true, true><<<grid, blk>>>(target, Wq, bq, Q,
                                                MTOT, EMB, EMB, 1.0f, 0, 0, 0);
        sgemm_kernel<true, true><<<grid, blk>>>(source, Wk, bk, K,
                                                MTOT, EMB, EMB, 1.0f, 0, 0, 0);
        sgemm_kernel<true, true><<<grid, blk>>>(source, Wv, bv, V,
                                                MTOT, EMB, EMB, 1.0f, 0, 0, 0);
    }

    // Scores: S[b] = Q[b] @ K[b]^T * scale   [2048,2048], batched over 8
    {
        dim3 grid(TSEQ / 128, TSEQ / 128, BATCH);
        sgemm_kernel<true, false><<<grid, blk>>>(
            Q, K, nullptr, S, TSEQ, TSEQ, EMB, scale,
            (size_t)TSEQ * EMB, (size_t)TSEQ * EMB, (size_t)TSEQ * TSEQ);
    }

    // Softmax over each of the 16384 rows of length 2048
    softmax_kernel<<<BATCH * TSEQ, blk>>>(S);

    // O[b] = P[b] @ V[b]   [2048,1024] = [2048,2048] @ [2048,1024], batched
    {
        dim3 grid(EMB / 128, TSEQ / 128, BATCH);
        sgemm_kernel<false, false><<<grid, blk>>>(
            S, V, nullptr, O, TSEQ, EMB, TSEQ, 1.0f,
            (size_t)TSEQ * TSEQ, (size_t)TSEQ * EMB, (size_t)TSEQ * EMB);
    }

    // Final projection: out = O @ Wo^T + bo
    {
        dim3 grid(EMB / 128, MTOT / 128, 1);
        sgemm_kernel<true, true><<<grid, blk>>>(O, Wo, bo, out,
                                                MTOT, EMB, EMB, 1.0f, 0, 0, 0);
    }
}

// round 7
// speedup vs baseline: 3.7950x; 3.7950x over previous
#include <cuda_runtime.h>
#include <cstdint>

// Cross attention B=8, Tq=Tk=2048, D=1024, fp32.
// All 6 GEMMs via mma.sync m16n8k8 tf32 (baseline PTX - no sm_103a needed).
// Operands pre-rounded to tf32 (rna) at producers => MMA truncation is exact.

#define BATCH 8
#define TSEQ  2048
#define EMB   1024
#define MTOT  (BATCH * TSEQ)          // 16384
#define NELEM ((size_t)MTOT * EMB)    // 16M

// ---------------- scratch (__device__ globals; no allocation) --------------
__device__ float g_T[NELEM];                         // tf32-rounded target
__device__ float g_Src[NELEM];                       // tf32-rounded source
__device__ float g_W[4u * EMB * EMB];                // rounded Wq,Wk,Wv,Wo
__device__ float g_Q[NELEM];
__device__ float g_K[NELEM];
__device__ float g_Vt[NELEM];                        // [B][EMB][TSEQ]
__device__ float g_S[(size_t)BATCH * TSEQ * TSEQ];   // scores, then P in-place
__device__ float g_O[NELEM];

// ---------------- helpers --------------------------------------------------
__device__ __forceinline__ uint32_t smem_u32(const void* p) {
    uint32_t a;
    asm("{ .reg .u64 t; cvta.to.shared.u64 t, %1; cvt.u32.u64 %0, t; }" : "=r"(a) : "l"(p));
    return a;
}
__device__ __forceinline__ float tf32r(float x) {
    uint32_t u;
    asm("cvt.rna.tf32.f32 %0, %1;" : "=r"(u) : "f"(x));
    return __uint_as_float(u);
}
#define CP_ASYNC16(dst, src) \
    asm volatile("cp.async.cg.shared.global [%0], [%1], 16;" :: "r"(dst), "l"(src) : "memory")
#define CP_COMMIT() asm volatile("cp.async.commit_group;" ::: "memory")

#define MMA_TF32(c, a, b) \
    asm volatile("mma.sync.aligned.m16n8k8.row.col.f32.tf32.tf32.f32 " \
        "{%0,%1,%2,%3}, {%4,%5,%6,%7}, {%8,%9}, {%0,%1,%2,%3};" \
        : "+f"((c)[0]), "+f"((c)[1]), "+f"((c)[2]), "+f"((c)[3]) \
        : "r"((a)[0]), "r"((a)[1]), "r"((a)[2]), "r"((a)[3]), "r"((b)[0]), "r"((b)[1]))

// ---------------------------------------------------------------------------
// tf32 GEMM (all-NT): C[M,N] = alpha * A[M,K] @ B[N,K]^T (+ bias[N])
// BM=128 BN=256 BK=32, 256 threads = 8 warps (2 M x 4 N), warp tile 64x64.
// 3-stage cp.async pipeline. SMEM rows padded to 36 floats (conflict-free:
// fragment lanes hit banks 4*group+tid4, all distinct).
// MODE 0: fp32 out. MODE 1: tf32-rounded fp32 out. MODE 2: rounded + transposed
//         out (Vt[b][col][tok], b = m0/TSEQ).
// ---------------------------------------------------------------------------
#define BM 128
#define BN 256
#define BK 32
#define STG_FLOATS 13824            // (128+256)*36
#define STG_BYTES  55296
#define GEMM_SMEM  (3 * STG_BYTES)  // 165888

template <int MODE, bool HAS_BIAS>
__global__ __launch_bounds__(256, 1)
void tf32_gemm(const float* __restrict__ A, const float* __restrict__ B,
               const float* __restrict__ bias, float* __restrict__ C,
               int M, int N, int K, float alpha,
               size_t sA, size_t sB, size_t sC)
{
    extern __shared__ float sm[];
    const uint32_t sb = smem_u32(sm);

    const int tid  = threadIdx.x;
    const int wid  = tid >> 5, lane = tid & 31;
    const int g    = lane >> 2, t4 = lane & 3;
    const int wm   = wid & 1,  wn = wid >> 1;

    const int m0 = blockIdx.y * BM;
    const int n0 = blockIdx.x * BN;
    A += (size_t)blockIdx.z * sA + (size_t)m0 * K;
    B += (size_t)blockIdx.z * sB + (size_t)n0 * K;

    auto load_stage = [&](int kt, int s) {
        const uint32_t st = sb + s * STG_BYTES;
        const int k0 = kt * BK;
#pragma unroll
        for (int i = 0; i < 4; i++) {          // A: 128 rows x 8 chunks
            int id = tid + i * 256, r = id >> 3, c = id & 7;
            CP_ASYNC16(st + (r * 36 + c * 4) * 4, A + (size_t)r * K + k0 + c * 4);
        }
#pragma unroll
        for (int i = 0; i < 8; i++) {          // B: 256 rows x 8 chunks
            int id = tid + i * 256, r = id >> 3, c = id & 7;
            CP_ASYNC16(st + 18432 + (r * 36 + c * 4) * 4, B + (size_t)r * K + k0 + c * 4);
        }
        CP_COMMIT();
    };

    float acc[4][8][4];
#pragma unroll
    for (int mi = 0; mi < 4; mi++)
#pragma unroll
        for (int ni = 0; ni < 8; ni++)
#pragma unroll
            for (int r = 0; r < 4; r++) acc[mi][ni][r] = 0.0f;

    const int KT = K / BK;
    load_stage(0, 0);
    load_stage(1, 1);
    load_stage(2, 2);

    for (int kt = 0; kt < KT; kt++) {
        asm volatile("cp.async.wait_group 2;" ::: "memory");
        __syncthreads();
        const int s = kt % 3;
        const float* As = sm + s * STG_FLOATS + (wm * 64 + g) * 36;
        const float* Bs = sm + s * STG_FLOATS + 4608 + (wn * 64 + g) * 36;

#pragma unroll
        for (int ks = 0; ks < 4; ks++) {
            uint32_t af[4][4], bf[8][2];
#pragma unroll
            for (int mi = 0; mi < 4; mi++) {
                const float* p = As + mi * 16 * 36 + ks * 8 + t4;
                af[mi][0] = __float_as_uint(p[0]);
                af[mi][1] = __float_as_uint(p[8 * 36]);
                af[mi][2] = __float_as_uint(p[4]);
                af[mi][3] = __float_as_uint(p[8 * 36 + 4]);
            }
#pragma unroll
            for (int ni = 0; ni < 8; ni++) {
                const float* p = Bs + ni * 8 * 36 + ks * 8 + t4;
                bf[ni][0] = __float_as_uint(p[0]);
                bf[ni][1] = __float_as_uint(p[4]);
            }
#pragma unroll
            for (int mi = 0; mi < 4; mi++)
#pragma unroll
                for (int ni = 0; ni < 8; ni++)
                    MMA_TF32(acc[mi][ni], af[mi], bf[ni]);
        }
        __syncthreads();
        if (kt + 3 < KT) load_stage(kt + 3, s);
    }

    // ---- epilogue ----
    if (MODE == 2) {
        // transposed + rounded: Vt[b][col][tok]
        float* Cb = C + (size_t)(m0 / TSEQ) * EMB * TSEQ;
        const int tokbase = (m0 % TSEQ) + wm * 64 + g;
#pragma unroll
        for (int mi = 0; mi < 4; mi++) {
            const int tok = tokbase + mi * 16;
#pragma unroll
            for (int ni = 0; ni < 8; ni++) {
                const int col = n0 + wn * 64 + ni * 8 + t4 * 2;
                float b0 = HAS_BIAS ? __ldg(bias + col)     : 0.0f;
                float b1 = HAS_BIAS ? __ldg(bias + col + 1) : 0.0f;
                Cb[(size_t)col * TSEQ + tok]           = tf32r(acc[mi][ni][0] * alpha + b0);
                Cb[(size_t)(col + 1) * TSEQ + tok]     = tf32r(acc[mi][ni][1] * alpha + b1);
                Cb[(size_t)col * TSEQ + tok + 8]       = tf32r(acc[mi][ni][2] * alpha + b0);
                Cb[(size_t)(col + 1) * TSEQ + tok + 8] = tf32r(acc[mi][ni][3] * alpha + b1);
            }
        }
    } else {
        C += (size_t)blockIdx.z * sC;
#pragma unroll
        for (int mi = 0; mi < 4; mi++) {
            const int row = m0 + wm * 64 + mi * 16 + g;
#pragma unroll
            for (int ni = 0; ni < 8; ni++) {
                const int col = n0 + wn * 64 + ni * 8 + t4 * 2;
                float b0 = HAS_BIAS ? __ldg(bias + col)     : 0.0f;
                float b1 = HAS_BIAS ? __ldg(bias + col + 1) : 0.0f;
                float f0 = acc[mi][ni][0] * alpha + b0;
                float f1 = acc[mi][ni][1] * alpha + b1;
                float f2 = acc[mi][ni][2] * alpha + b0;
                float f3 = acc[mi][ni][3] * alpha + b1;
                if (MODE == 1) { f0 = tf32r(f0); f1 = tf32r(f1); f2 = tf32r(f2); f3 = tf32r(f3); }
                *reinterpret_cast<float2*>(C + (size_t)row * N + col)       = make_float2(f0, f1);
                *reinterpret_cast<float2*>(C + (size_t)(row + 8) * N + col) = make_float2(f2, f3);
            }
        }
    }
}

// ---------------------------------------------------------------------------
// elementwise tf32 rounding pass (for raw inputs / weights)
// ---------------------------------------------------------------------------
__global__ void round_kernel(const float4* __restrict__ x, float4* __restrict__ y, int n4)
{
    int i = blockIdx.x * blockDim.x + threadIdx.x;
    if (i >= n4) return;
    float4 v = x[i];
    v.x = tf32r(v.x); v.y = tf32r(v.y); v.z = tf32r(v.z); v.w = tf32r(v.w);
    y[i] = v;
}

// ---------------------------------------------------------------------------
// softmax over 2048-length rows (in place), output tf32-rounded
// ---------------------------------------------------------------------------
__device__ __forceinline__ float blk_red_max(float v) {
    __shared__ float sh[8]; __shared__ float res;
    const int lane = threadIdx.x & 31, warp = threadIdx.x >> 5;
#pragma unroll
    for (int o = 16; o > 0; o >>= 1) v = fmaxf(v, __shfl_xor_sync(0xffffffffu, v, o));
    if (lane == 0) sh[warp] = v;
    __syncthreads();
    if (warp == 0) {
        float w = (lane < 8) ? sh[lane] : -3.0e38f;
#pragma unroll
        for (int o = 4; o > 0; o >>= 1) w = fmaxf(w, __shfl_xor_sync(0xffffffffu, w, o));
        if (lane == 0) res = w;
    }
    __syncthreads();
    return res;
}
__device__ __forceinline__ float blk_red_sum(float v) {
    __shared__ float sh[8]; __shared__ float res;
    const int lane = threadIdx.x & 31, warp = threadIdx.x >> 5;
#pragma unroll
    for (int o = 16; o > 0; o >>= 1) v += __shfl_xor_sync(0xffffffffu, v, o);
    if (lane == 0) sh[warp] = v;
    __syncthreads();
    if (warp == 0) {
        float w = (lane < 8) ? sh[lane] : 0.0f;
#pragma unroll
        for (int o = 4; o > 0; o >>= 1) w += __shfl_xor_sync(0xffffffffu, w, o);
        if (lane == 0) res = w;
    }
    __syncthreads();
    return res;
}

__global__ __launch_bounds__(256)
void softmax_kernel(float* __restrict__ S)
{
    float4* row = reinterpret_cast<float4*>(S + (size_t)blockIdx.x * TSEQ);
    const int t = threadIdx.x;

    float4 v0 = row[t];
    float4 v1 = row[t + 256];

    float mx = fmaxf(fmaxf(fmaxf(v0.x, v0.y), fmaxf(v0.z, v0.w)),
                     fmaxf(fmaxf(v1.x, v1.y), fmaxf(v1.z, v1.w)));
    mx = blk_red_max(mx);

    v0.x = __expf(v0.x - mx); v0.y = __expf(v0.y - mx);
    v0.z = __expf(v0.z - mx); v0.w = __expf(v0.w - mx);
    v1.x = __expf(v1.x - mx); v1.y = __expf(v1.y - mx);
    v1.z = __expf(v1.z - mx); v1.w = __expf(v1.w - mx);

    float s = (v0.x + v0.y + v0.z + v0.w) + (v1.x + v1.y + v1.z + v1.w);
    s = blk_red_sum(s);
    const float inv = 1.0f / s;

    v0.x = tf32r(v0.x * inv); v0.y = tf32r(v0.y * inv);
    v0.z = tf32r(v0.z * inv); v0.w = tf32r(v0.w * inv);
    v1.x = tf32r(v1.x * inv); v1.y = tf32r(v1.y * inv);
    v1.z = tf32r(v1.z * inv); v1.w = tf32r(v1.w * inv);
    row[t]       = v0;
    row[t + 256] = v1;
}

// ---------------------------------------------------------------------------
extern "C" void kernel_launch(void* const* d_in, const int* in_sizes, int n_in,
                              void* d_out, int out_size)
{
    const float* target = (const float*)d_in[0];
    const float* source = (const float*)d_in[1];
    const float* Wq = (const float*)d_in[2];
    const float* bq = (const float*)d_in[3];
    const float* Wk = (const float*)d_in[4];
    const float* bk = (const float*)d_in[5];
    const float* Wv = (const float*)d_in[6];
    const float* bv = (const float*)d_in[7];
    const float* Wo = (const float*)d_in[8];
    const float* bo = (const float*)d_in[9];
    float* out = (float*)d_out;

    float *T, *Src, *W, *Q, *Kb, *Vt, *S, *O;
    cudaGetSymbolAddress((void**)&T,   g_T);
    cudaGetSymbolAddress((void**)&Src, g_Src);
    cudaGetSymbolAddress((void**)&W,   g_W);
    cudaGetSymbolAddress((void**)&Q,   g_Q);
    cudaGetSymbolAddress((void**)&Kb,  g_K);
    cudaGetSymbolAddress((void**)&Vt,  g_Vt);
    cudaGetSymbolAddress((void**)&S,   g_S);
    cudaGetSymbolAddress((void**)&O,   g_O);

    cudaFuncSetAttribute(tf32_gemm<0, false>, cudaFuncAttributeMaxDynamicSharedMemorySize, GEMM_SMEM);
    cudaFuncSetAttribute(tf32_gemm<0, true>,  cudaFuncAttributeMaxDynamicSharedMemorySize, GEMM_SMEM);
    cudaFuncSetAttribute(tf32_gemm<1, false>, cudaFuncAttributeMaxDynamicSharedMemorySize, GEMM_SMEM);
    cudaFuncSetAttribute(tf32_gemm<1, true>,  cudaFuncAttributeMaxDynamicSharedMemorySize, GEMM_SMEM);
    cudaFuncSetAttribute(tf32_gemm<2, true>,  cudaFuncAttributeMaxDynamicSharedMemorySize, GEMM_SMEM);

    // tf32-round inputs & weights
    round_kernel<<<(int)(NELEM / 4 / 256), 256>>>((const float4*)target, (float4*)T,   (int)(NELEM / 4));
    round_kernel<<<(int)(NELEM / 4 / 256), 256>>>((const float4*)source, (float4*)Src, (int)(NELEM / 4));
    const int wn4 = EMB * EMB / 4;
    round_kernel<<<wn4 / 256, 256>>>((const float4*)Wq, (float4*)(W + 0u * EMB * EMB), wn4);
    round_kernel<<<wn4 / 256, 256>>>((const float4*)Wk, (float4*)(W + 1u * EMB * EMB), wn4);
    round_kernel<<<wn4 / 256, 256>>>((const float4*)Wv, (float4*)(W + 2u * EMB * EMB), wn4);
    round_kernel<<<wn4 / 256, 256>>>((const float4*)Wo, (float4*)(W + 3u * EMB * EMB), wn4);

    const float scale = 1.0f / 32.0f;  // 1/sqrt(1024)

    // projections (rounded outputs)
    {
        dim3 grd(EMB / BN, MTOT / BM, 1);
        tf32_gemm<1, true><<<grd, 256, GEMM_SMEM>>>(T,   W + 0u * EMB * EMB, bq, Q,
                                                    MTOT, EMB, EMB, 1.0f, 0, 0, 0);
        tf32_gemm<1, true><<<grd, 256, GEMM_SMEM>>>(Src, W + 1u * EMB * EMB, bk, Kb,
                                                    MTOT, EMB, EMB, 1.0f, 0, 0, 0);
        tf32_gemm<2, true><<<grd, 256, GEMM_SMEM>>>(Src, W + 2u * EMB * EMB, bv, Vt,
                                                    MTOT, EMB, EMB, 1.0f, 0, 0, 0);
    }

    // S = Q @ K^T / 32 (batched)
    {
        dim3 grd(TSEQ / BN, TSEQ / BM, BATCH);
        tf32_gemm<0, false><<<grd, 256, GEMM_SMEM>>>(Q, Kb, nullptr, S,
            TSEQ, TSEQ, EMB, scale,
            (size_t)TSEQ * EMB, (size_t)TSEQ * EMB, (size_t)TSEQ * TSEQ);
    }

    // P = softmax(S), tf32-rounded, in place
    softmax_kernel<<<BATCH * TSEQ, 256>>>(S);

    // O = P @ Vt^T (batched, K=2048)
    {
        dim3 grd(EMB / BN, TSEQ / BM, BATCH);
        tf32_gemm<1, false><<<grd, 256, GEMM_SMEM>>>(S, Vt, nullptr, O,
            TSEQ, EMB, TSEQ, 1.0f,
            (size_t)TSEQ * TSEQ, (size_t)EMB * TSEQ, (size_t)TSEQ * EMB);
    }

    // out = O @ Wo^T + bo (fp32)
    {
        dim3 grd(EMB / BN, MTOT / BM, 1);
        tf32_gemm<0, true><<<grd, 256, GEMM_SMEM>>>(O, W + 3u * EMB * EMB, bo, out,
                                                    MTOT, EMB, EMB, 1.0f, 0, 0, 0);
    }
}